// round 10
// baseline (speedup 1.0000x reference)
#include <cuda_runtime.h>
#include <math.h>

#define L    8192
#define CC   512
#define MM   1024
#define HH   16
#define WWID 512
#define NHEADS 4
#define DHEAD  128
#define MP_EPS 1e-4f

// ---------------- scratch (static device allocations; no cudaMalloc) ----------------
__device__ float g_xn[CC * L];    // normalized x
__device__ float g_y0[MM * L];    // res0 output
__device__ float g_y2[MM * L];    // depth conv + silu output
__device__ float g_x1[CC * L];    // x after mp_sum with residual branch
__device__ float g_pe[MM * L];    // interleaved [x, x*pos]
__device__ float g_qk[MM * L];    // qk conv output (pre-norm)
__device__ float g_q[CC * L];     // packed q [h][d][L]
__device__ float g_k[CC * L];     // packed k [h][d][L]
__device__ float g_v[CC * L];     // v (normalized in place) [h*128+d][L]
__device__ float g_c[MM];         // embedding modulation vector

// ---------------- normalize x over channels (per pixel) ----------------
__global__ void norm_x_k(const float* __restrict__ x, float* __restrict__ xn) {
    int l = blockIdx.x * 256 + threadIdx.x;
    float s = 0.f;
#pragma unroll 8
    for (int c = 0; c < CC; c++) { float v = x[c * L + l]; s += v * v; }
    float inv = 1.f / (MP_EPS + sqrtf(s) * 0.044194173824159216f); // 1/sqrt(512)
#pragma unroll 8
    for (int c = 0; c < CC; c++) xn[c * L + l] = x[c * L + l] * inv;
}

// ---------------- c[m] = emb_gain/sqrt(512) * (w_emb[m] . emb) + 1 ----------------
__global__ void emb_k(const float* __restrict__ emb, const float* __restrict__ wemb,
                      const float* __restrict__ gain, float* __restrict__ cvec) {
    int m = blockIdx.x * 8 + (threadIdx.x >> 5);
    int lane = threadIdx.x & 31;
    float s = 0.f;
    for (int e = lane; e < 512; e += 32) s += wemb[m * 512 + e] * emb[e];
#pragma unroll
    for (int off = 16; off; off >>= 1) s += __shfl_xor_sync(0xffffffffu, s, off);
    if (lane == 0) cvec[m] = gain[0] * 0.044194173824159216f * s + 1.f;
}

// ---------------- SGEMM: C[M,N] = scale * A[M,K] @ B[K,N] ----------------
// EPI=0: plain store.  EPI=1: res1 epilogue -> x1 = (xn + y)/sqrt2 ; pe interleave.
template <int EPI>
__global__ void __launch_bounds__(256) sgemm_k(
    const float* __restrict__ A, const float* __restrict__ B, float* __restrict__ C,
    int M, int N, int K, float scale,
    const float* __restrict__ xn, const float* __restrict__ pos, float* __restrict__ pe) {
    __shared__ float As[8][132];
    __shared__ float Bs[8][128];
    const int tid = threadIdx.x;
    const int row0 = blockIdx.y * 128, col0 = blockIdx.x * 128;
    const int arow = tid >> 1, acol = (tid & 1) * 4;
    const int brow = tid >> 5, bcol = (tid & 31) * 4;
    const int ty = tid >> 4, tx = tid & 15;

    float acc[8][8];
#pragma unroll
    for (int i = 0; i < 8; i++)
#pragma unroll
        for (int j = 0; j < 8; j++) acc[i][j] = 0.f;

    const float* Aptr = A + (row0 + arow) * K + acol;
    const float* Bptr = B + brow * N + col0 + bcol;

    for (int k0 = 0; k0 < K; k0 += 8) {
        float4 av = *(const float4*)(Aptr + k0);
        float4 bv = *(const float4*)(Bptr + (size_t)k0 * N);
        As[acol + 0][arow] = av.x;
        As[acol + 1][arow] = av.y;
        As[acol + 2][arow] = av.z;
        As[acol + 3][arow] = av.w;
        *(float4*)&Bs[brow][bcol] = bv;
        __syncthreads();
#pragma unroll
        for (int kk = 0; kk < 8; kk++) {
            float a[8], b[8];
            *(float4*)(a)     = *(const float4*)&As[kk][ty * 8];
            *(float4*)(a + 4) = *(const float4*)&As[kk][ty * 8 + 4];
            *(float4*)(b)     = *(const float4*)&Bs[kk][tx * 8];
            *(float4*)(b + 4) = *(const float4*)&Bs[kk][tx * 8 + 4];
#pragma unroll
            for (int i = 0; i < 8; i++)
#pragma unroll
                for (int j = 0; j < 8; j++) acc[i][j] += a[i] * b[j];
        }
        __syncthreads();
    }

#pragma unroll
    for (int i = 0; i < 8; i++) {
        int r = row0 + ty * 8 + i;
        int cbase = col0 + tx * 8;
        if (EPI == 0) {
            float4 o0, o1;
            o0.x = acc[i][0] * scale; o0.y = acc[i][1] * scale;
            o0.z = acc[i][2] * scale; o0.w = acc[i][3] * scale;
            o1.x = acc[i][4] * scale; o1.y = acc[i][5] * scale;
            o1.z = acc[i][6] * scale; o1.w = acc[i][7] * scale;
            *(float4*)&C[(size_t)r * N + cbase]     = o0;
            *(float4*)&C[(size_t)r * N + cbase + 4] = o1;
        } else {
#pragma unroll
            for (int j = 0; j < 8; j++) {
                int n = cbase + j;
                float val = (xn[(size_t)r * N + n] + acc[i][j] * scale) * 0.7071067811865476f;
                C[(size_t)r * N + n] = val;
                pe[(size_t)(2 * r) * N + n] = val;
                pe[(size_t)(2 * r + 1) * N + n] = val * pos[(size_t)r * N + n];
            }
        }
    }
}

// ---------------- grouped (1,9) conv + c-mod + mp_silu, fused ----------------
// grid: (wtile=8, h=16, group=8), 256 threads. Block computes 128 m x 64 w.
__global__ void __launch_bounds__(256) depth_k(const float* __restrict__ y0,
                                               const float* __restrict__ wd,
                                               const float* __restrict__ cvec,
                                               float* __restrict__ y2) {
    __shared__ float ws[1152];   // weights for all 128 m at current ci (9 taps each)
    __shared__ float in_row[72]; // input row segment (64 + 8 halo)
    const int tid = threadIdx.x;
    const int wt = blockIdx.x, h = blockIdx.y, g = blockIdx.z;
    const int tm = tid >> 4, tw = tid & 15; // tm: 8-m block (0..15), tw: 4-w block (0..15)

    float acc[8][4];
#pragma unroll
    for (int i = 0; i < 8; i++)
#pragma unroll
        for (int w = 0; w < 4; w++) acc[i][w] = 0.f;

    const float* wbase = wd + (size_t)g * 128 * 1152;
    const float* ybase = y0 + (size_t)(g * 128) * L + h * WWID;

    for (int ci = 0; ci < 128; ci++) {
        __syncthreads();
        for (int idx = tid; idx < 1152; idx += 256)
            ws[idx] = wbase[(idx / 9) * 1152 + ci * 9 + (idx % 9)];
        if (tid < 72) {
            int w = wt * 64 - 4 + tid;
            in_row[tid] = ((unsigned)w < WWID) ? ybase[(size_t)ci * L + w] : 0.f;
        }
        __syncthreads();

        float iv[12];
#pragma unroll
        for (int q = 0; q < 12; q++) iv[q] = in_row[tw * 4 + q];
#pragma unroll
        for (int t = 0; t < 9; t++) {
#pragma unroll
            for (int i = 0; i < 8; i++) {
                float wv = ws[(tm * 8 + i) * 9 + t];
                acc[i][0] += wv * iv[t + 0];
                acc[i][1] += wv * iv[t + 1];
                acc[i][2] += wv * iv[t + 2];
                acc[i][3] += wv * iv[t + 3];
            }
        }
    }

    const float wsc = 0.029462782549439476f; // 1/sqrt(1152)
#pragma unroll
    for (int i = 0; i < 8; i++) {
        int m = g * 128 + tm * 8 + i;
        float cm = cvec[m];
        float4 o;
        float* po = (float*)&o;
#pragma unroll
        for (int w = 0; w < 4; w++) {
            float val = acc[i][w] * wsc * cm;
            float sg = 1.f / (1.f + __expf(-val));
            po[w] = val * sg * 1.6778523489932886f; // silu / 0.596
        }
        *(float4*)&y2[(size_t)m * L + h * WWID + wt * 64 + tw * 4] = o;
    }
}

// ---------------- normalize qk over d, split + pack q/k as [h][d][L] ----------------
__global__ void qknorm_k(const float* __restrict__ qk, float* __restrict__ qo,
                         float* __restrict__ ko) {
    int l = blockIdx.x * 256 + threadIdx.x;
    int h = blockIdx.y >> 1, s = blockIdx.y & 1;
    const float* base = qk + (size_t)(h * 256 + s) * L + l;
    float sum = 0.f;
#pragma unroll 8
    for (int d = 0; d < 128; d++) { float v = base[(size_t)d * 2 * L]; sum += v * v; }
    float inv = 1.f / (MP_EPS + sqrtf(sum) * 0.08838834764831845f); // 1/sqrt(128)
    float* out = (s ? ko : qo) + (size_t)h * 128 * L + l;
#pragma unroll 8
    for (int d = 0; d < 128; d++) out[(size_t)d * L] = base[(size_t)d * 2 * L] * inv;
}

// ---------------- normalize v over d, in place ----------------
__global__ void vnorm_k(float* __restrict__ v) {
    int l = blockIdx.x * 256 + threadIdx.x;
    int h = blockIdx.y;
    float* base = v + (size_t)h * 128 * L + l;
    float sum = 0.f;
#pragma unroll 8
    for (int d = 0; d < 128; d++) { float t = base[(size_t)d * L]; sum += t * t; }
    float inv = 1.f / (MP_EPS + sqrtf(sum) * 0.08838834764831845f);
#pragma unroll 8
    for (int d = 0; d < 128; d++) base[(size_t)d * L] *= inv;
}

// ---------------- flash attention, fp32, fused final mp_sum + clip ----------------
// grid: (qtile=128, head=4), 256 threads. BQ=BKV=64.
// Shared strides padded to multiples of 4 floats so all float4 accesses are 16B-aligned.
#define VS_STRIDE 132
#define PS_STRIDE 68
__global__ void __launch_bounds__(256) attn_k(
    const float* __restrict__ q, const float* __restrict__ k, const float* __restrict__ v,
    const float* __restrict__ x1, float* __restrict__ out) {
    extern __shared__ float sm[];
    float* qs = sm;                           // [128][64]
    float* ks = sm + 8192;                    // [128][64]
    float* vs = sm + 16384;                   // [64][VS_STRIDE] (transposed, padded)
    float* ps = vs + 64 * VS_STRIDE;          // [64][PS_STRIDE] (padded)
    const int tid = threadIdx.x;
    const int hd = blockIdx.y, qt = blockIdx.x;
    const int tq = tid >> 4, tk = tid & 15;
    const float* qh = q + (size_t)hd * 128 * L + qt * 64;
    const float* kh = k + (size_t)hd * 128 * L;
    const float* vh = v + (size_t)hd * 128 * L;

    // load q tile with 1/sqrt(d) folded in
    for (int idx = tid * 4; idx < 8192; idx += 1024) {
        int d = idx >> 6, i = idx & 63;
        float4 t = *(const float4*)(qh + (size_t)d * L + i);
        t.x *= 0.08838834764831845f; t.y *= 0.08838834764831845f;
        t.z *= 0.08838834764831845f; t.w *= 0.08838834764831845f;
        *(float4*)(qs + idx) = t;
    }

    float o[4][8];
#pragma unroll
    for (int r = 0; r < 4; r++)
#pragma unroll
        for (int d = 0; d < 8; d++) o[r][d] = 0.f;
    float mrow[4] = {-1e30f, -1e30f, -1e30f, -1e30f};
    float lrow[4] = {0.f, 0.f, 0.f, 0.f};

    for (int kt = 0; kt < 128; kt++) {
        __syncthreads(); // previous PV done before overwriting ks/vs (also covers qs store)
        for (int idx = tid * 4; idx < 8192; idx += 1024) {
            int d = idx >> 6, j = idx & 63;
            *(float4*)(ks + idx) = *(const float4*)(kh + (size_t)d * L + kt * 64 + j);
            float4 t = *(const float4*)(vh + (size_t)d * L + kt * 64 + j);
            vs[(j + 0) * VS_STRIDE + d] = t.x;
            vs[(j + 1) * VS_STRIDE + d] = t.y;
            vs[(j + 2) * VS_STRIDE + d] = t.z;
            vs[(j + 3) * VS_STRIDE + d] = t.w;
        }
        __syncthreads();

        // S = q^T k   (4x4 per thread)
        float s4[4][4];
#pragma unroll
        for (int r = 0; r < 4; r++)
#pragma unroll
            for (int c = 0; c < 4; c++) s4[r][c] = 0.f;
#pragma unroll 4
        for (int d = 0; d < 128; d++) {
            float4 a = *(const float4*)(qs + d * 64 + tq * 4);
            float4 b = *(const float4*)(ks + d * 64 + tk * 4);
            s4[0][0] += a.x * b.x; s4[0][1] += a.x * b.y; s4[0][2] += a.x * b.z; s4[0][3] += a.x * b.w;
            s4[1][0] += a.y * b.x; s4[1][1] += a.y * b.y; s4[1][2] += a.y * b.z; s4[1][3] += a.y * b.w;
            s4[2][0] += a.z * b.x; s4[2][1] += a.z * b.y; s4[2][2] += a.z * b.z; s4[2][3] += a.z * b.w;
            s4[3][0] += a.w * b.x; s4[3][1] += a.w * b.y; s4[3][2] += a.w * b.z; s4[3][3] += a.w * b.w;
        }

        // online softmax (rows live in 16-lane groups: same tq)
#pragma unroll
        for (int r = 0; r < 4; r++) {
            float* sr = s4[r];
            float mx = fmaxf(fmaxf(sr[0], sr[1]), fmaxf(sr[2], sr[3]));
#pragma unroll
            for (int off = 8; off; off >>= 1) mx = fmaxf(mx, __shfl_xor_sync(0xffffffffu, mx, off, 16));
            float mnew = fmaxf(mrow[r], mx);
            float corr = __expf(mrow[r] - mnew);
            float rs = 0.f;
#pragma unroll
            for (int c = 0; c < 4; c++) { float p = __expf(sr[c] - mnew); sr[c] = p; rs += p; }
#pragma unroll
            for (int off = 8; off; off >>= 1) rs += __shfl_xor_sync(0xffffffffu, rs, off, 16);
            lrow[r] = lrow[r] * corr + rs;
            mrow[r] = mnew;
#pragma unroll
            for (int d = 0; d < 8; d++) o[r][d] *= corr;
#pragma unroll
            for (int c = 0; c < 4; c++) ps[(tk * 4 + c) * PS_STRIDE + tq * 4 + r] = sr[c];
        }
        __syncwarp(); // P producers/consumers for a given tq share a warp

        // O += P @ V^T  (4 rows x 8 d-cols per thread)
#pragma unroll 2
        for (int j = 0; j < 64; j++) {
            float4 p4 = *(const float4*)(ps + j * PS_STRIDE + tq * 4);
            float4 v0 = *(const float4*)(vs + j * VS_STRIDE + tk * 4);
            float4 v1 = *(const float4*)(vs + j * VS_STRIDE + 64 + tk * 4);
            float pa[4] = {p4.x, p4.y, p4.z, p4.w};
#pragma unroll
            for (int r = 0; r < 4; r++) {
                o[r][0] += pa[r] * v0.x; o[r][1] += pa[r] * v0.y;
                o[r][2] += pa[r] * v0.z; o[r][3] += pa[r] * v0.w;
                o[r][4] += pa[r] * v1.x; o[r][5] += pa[r] * v1.y;
                o[r][6] += pa[r] * v1.z; o[r][7] += pa[r] * v1.w;
            }
        }
    }

    // epilogue: normalize, residual mp_sum, clip, store
#pragma unroll
    for (int r = 0; r < 4; r++) {
        float invl = 1.f / lrow[r];
        int i = qt * 64 + tq * 4 + r;
#pragma unroll
        for (int half = 0; half < 2; half++) {
#pragma unroll
            for (int c = 0; c < 4; c++) {
                int dd = half * 64 + tk * 4 + c;
                int ch = hd * 128 + dd;
                float val = o[r][half * 4 + c] * invl;
                float res = (x1[(size_t)ch * L + i] + val) * 0.7071067811865476f;
                res = fminf(fmaxf(res, -256.f), 256.f);
                out[(size_t)ch * L + i] = res;
            }
        }
    }
}

// ---------------- launch ----------------
extern "C" void kernel_launch(void* const* d_in, const int* in_sizes, int n_in,
                              void* d_out, int out_size) {
    const float* x      = (const float*)d_in[0];
    const float* emb    = (const float*)d_in[1];
    const float* pos    = (const float*)d_in[2];
    const float* egain  = (const float*)d_in[3];
    const float* w_res0 = (const float*)d_in[4];
    const float* w_dep  = (const float*)d_in[5];
    const float* w_emb  = (const float*)d_in[6];
    const float* w_res1 = (const float*)d_in[7];
    const float* w_qk   = (const float*)d_in[8];
    const float* w_v    = (const float*)d_in[9];
    float* outp = (float*)d_out;

    float *xn, *y0, *y2, *x1, *pe, *qkb, *qb, *kb, *vb, *cv;
    cudaGetSymbolAddress((void**)&xn, g_xn);
    cudaGetSymbolAddress((void**)&y0, g_y0);
    cudaGetSymbolAddress((void**)&y2, g_y2);
    cudaGetSymbolAddress((void**)&x1, g_x1);
    cudaGetSymbolAddress((void**)&pe, g_pe);
    cudaGetSymbolAddress((void**)&qkb, g_qk);
    cudaGetSymbolAddress((void**)&qb, g_q);
    cudaGetSymbolAddress((void**)&kb, g_k);
    cudaGetSymbolAddress((void**)&vb, g_v);
    cudaGetSymbolAddress((void**)&cv, g_c);

    const float rs512  = 0.044194173824159216f; // 1/sqrt(512)
    const float rs1024 = 0.03125f;              // 1/sqrt(1024)

    norm_x_k<<<32, 256>>>(x, xn);
    emb_k<<<128, 256>>>(emb, w_emb, egain, cv);

    // y0 = res0(xn): [1024,512] @ [512,L]
    sgemm_k<0><<<dim3(64, 8), 256>>>(w_res0, xn, y0, MM, L, CC, rs512, 0, 0, 0);
    // depth conv + c-mod + silu
    depth_k<<<dim3(8, 16, 8), 256>>>(y0, w_dep, cv, y2);
    // x1 = (xn + res1(y2))/sqrt2 ; pe interleave. [512,1024] @ [1024,L]
    sgemm_k<1><<<dim3(64, 4), 256>>>(w_res1, y2, x1, CC, L, MM, rs1024, xn, pos, pe);
    // qk = Wqk @ pe: [1024,1024] @ [1024,L]
    sgemm_k<0><<<dim3(64, 8), 256>>>(w_qk, pe, qkb, MM, L, MM, rs1024, 0, 0, 0);
    // v = Wv @ x1: [512,512] @ [512,L]
    sgemm_k<0><<<dim3(64, 4), 256>>>(w_v, x1, vb, CC, L, CC, rs512, 0, 0, 0);

    qknorm_k<<<dim3(32, 8), 256>>>(qkb, qb, kb);
    vnorm_k<<<dim3(32, 4), 256>>>(vb);

    const int SMEM = (8192 + 8192 + 64 * VS_STRIDE + 64 * PS_STRIDE) * 4; // 116736 B
    cudaFuncSetAttribute(attn_k, cudaFuncAttributeMaxDynamicSharedMemorySize, SMEM);
    attn_k<<<dim3(128, 4), 256, SMEM>>>(qb, kb, vb, x1, outp);
}

// round 12
// speedup vs baseline: 2.6757x; 2.6757x over previous
#include <cuda_runtime.h>
#include <math.h>

#define L    8192
#define CC   512
#define MM   1024
#define HH   16
#define WWID 512
#define NHEADS 4
#define DHEAD  128
#define MP_EPS 1e-4f

// ---------------- scratch (static device allocations; no cudaMalloc) ----------------
__device__ float g_xn[CC * L];    // normalized x
__device__ float g_y0[MM * L];    // res0 output
__device__ float g_y2[MM * L];    // depth conv + silu output
__device__ float g_x1[CC * L];    // x after mp_sum with residual branch
__device__ float g_pe[MM * L];    // interleaved [x, x*pos]
__device__ float g_qk[MM * L];    // qk conv output (pre-norm)
__device__ float g_q[CC * L];     // packed q [h][d][L]
__device__ float g_k[CC * L];     // packed k [h][d][L]
__device__ float g_v[CC * L];     // v (normalized in place) [h*128+d][L]
__device__ float g_c[MM];         // embedding modulation vector

__device__ __forceinline__ float tf32r(float x) {
    float r;
    asm("cvt.rna.tf32.f32 %0, %1;" : "=f"(r) : "f"(x));
    return r;
}

// ---------------- normalize x over channels (per pixel) ----------------
__global__ void norm_x_k(const float* __restrict__ x, float* __restrict__ xn) {
    int l = blockIdx.x * 256 + threadIdx.x;
    float s = 0.f;
#pragma unroll 8
    for (int c = 0; c < CC; c++) { float v = x[c * L + l]; s += v * v; }
    float inv = 1.f / (MP_EPS + sqrtf(s) * 0.044194173824159216f); // 1/sqrt(512)
#pragma unroll 8
    for (int c = 0; c < CC; c++) xn[c * L + l] = x[c * L + l] * inv;
}

// ---------------- c[m] = emb_gain/sqrt(512) * (w_emb[m] . emb) + 1 ----------------
__global__ void emb_k(const float* __restrict__ emb, const float* __restrict__ wemb,
                      const float* __restrict__ gain, float* __restrict__ cvec) {
    int m = blockIdx.x * 8 + (threadIdx.x >> 5);
    int lane = threadIdx.x & 31;
    float s = 0.f;
    for (int e = lane; e < 512; e += 32) s += wemb[m * 512 + e] * emb[e];
#pragma unroll
    for (int off = 16; off; off >>= 1) s += __shfl_xor_sync(0xffffffffu, s, off);
    if (lane == 0) cvec[m] = gain[0] * 0.044194173824159216f * s + 1.f;
}

// ---------------- SGEMM: C[M,N] = scale * A[M,K] @ B[K,N] ----------------
template <int EPI>
__global__ void __launch_bounds__(256) sgemm_k(
    const float* __restrict__ A, const float* __restrict__ B, float* __restrict__ C,
    int M, int N, int K, float scale,
    const float* __restrict__ xn, const float* __restrict__ pos, float* __restrict__ pe) {
    __shared__ float As[8][132];
    __shared__ float Bs[8][128];
    const int tid = threadIdx.x;
    const int row0 = blockIdx.y * 128, col0 = blockIdx.x * 128;
    const int arow = tid >> 1, acol = (tid & 1) * 4;
    const int brow = tid >> 5, bcol = (tid & 31) * 4;
    const int ty = tid >> 4, tx = tid & 15;

    float acc[8][8];
#pragma unroll
    for (int i = 0; i < 8; i++)
#pragma unroll
        for (int j = 0; j < 8; j++) acc[i][j] = 0.f;

    const float* Aptr = A + (row0 + arow) * K + acol;
    const float* Bptr = B + brow * N + col0 + bcol;

    for (int k0 = 0; k0 < K; k0 += 8) {
        float4 av = *(const float4*)(Aptr + k0);
        float4 bv = *(const float4*)(Bptr + (size_t)k0 * N);
        As[acol + 0][arow] = av.x;
        As[acol + 1][arow] = av.y;
        As[acol + 2][arow] = av.z;
        As[acol + 3][arow] = av.w;
        *(float4*)&Bs[brow][bcol] = bv;
        __syncthreads();
#pragma unroll
        for (int kk = 0; kk < 8; kk++) {
            float a[8], b[8];
            *(float4*)(a)     = *(const float4*)&As[kk][ty * 8];
            *(float4*)(a + 4) = *(const float4*)&As[kk][ty * 8 + 4];
            *(float4*)(b)     = *(const float4*)&Bs[kk][tx * 8];
            *(float4*)(b + 4) = *(const float4*)&Bs[kk][tx * 8 + 4];
#pragma unroll
            for (int i = 0; i < 8; i++)
#pragma unroll
                for (int j = 0; j < 8; j++) acc[i][j] += a[i] * b[j];
        }
        __syncthreads();
    }

#pragma unroll
    for (int i = 0; i < 8; i++) {
        int r = row0 + ty * 8 + i;
        int cbase = col0 + tx * 8;
        if (EPI == 0) {
            float4 o0, o1;
            o0.x = acc[i][0] * scale; o0.y = acc[i][1] * scale;
            o0.z = acc[i][2] * scale; o0.w = acc[i][3] * scale;
            o1.x = acc[i][4] * scale; o1.y = acc[i][5] * scale;
            o1.z = acc[i][6] * scale; o1.w = acc[i][7] * scale;
            *(float4*)&C[(size_t)r * N + cbase]     = o0;
            *(float4*)&C[(size_t)r * N + cbase + 4] = o1;
        } else {
#pragma unroll
            for (int j = 0; j < 8; j++) {
                int n = cbase + j;
                float val = (xn[(size_t)r * N + n] + acc[i][j] * scale) * 0.7071067811865476f;
                C[(size_t)r * N + n] = val;
                pe[(size_t)(2 * r) * N + n] = val;
                pe[(size_t)(2 * r + 1) * N + n] = val * pos[(size_t)r * N + n];
            }
        }
    }
}

// ---------------- grouped (1,9) conv + c-mod + mp_silu, fused (ci tiled by 4) ----------------
// grid: (wtile=8, h=16, group=8), 256 threads. Block computes 128 m x 64 w.
__global__ void __launch_bounds__(256) depth_k(const float* __restrict__ y0,
                                               const float* __restrict__ wd,
                                               const float* __restrict__ cvec,
                                               float* __restrict__ y2) {
    __shared__ float ws[4608];      // [m 128][cio 4][tap 9]
    __shared__ float in_row[4][72]; // 4 input rows (64 + 8 halo)
    const int tid = threadIdx.x;
    const int wt = blockIdx.x, h = blockIdx.y, g = blockIdx.z;
    const int tm = tid >> 4, tw = tid & 15;

    float acc[8][4];
#pragma unroll
    for (int i = 0; i < 8; i++)
#pragma unroll
        for (int w = 0; w < 4; w++) acc[i][w] = 0.f;

    const float* wbase = wd + (size_t)g * 128 * 1152;
    const float* ybase = y0 + (size_t)(g * 128) * L + h * WWID;

    for (int ci0 = 0; ci0 < 128; ci0 += 4) {
        __syncthreads();
#pragma unroll
        for (int q = tid; q < 512; q += 256) {
            int m = q >> 2, cio = q & 3;
            const float* src = wbase + m * 1152 + (ci0 + cio) * 9;
            float* dst = ws + (m * 4 + cio) * 9;
#pragma unroll
            for (int t = 0; t < 9; t++) dst[t] = src[t];
        }
        // 288 halo elements, 256 threads -> strided loop (NOT a single if!)
        for (int q = tid; q < 288; q += 256) {
            int cio = q / 72, off = q - cio * 72;
            int w = wt * 64 - 4 + off;
            in_row[cio][off] = ((unsigned)w < WWID) ? ybase[(size_t)(ci0 + cio) * L + w] : 0.f;
        }
        __syncthreads();
#pragma unroll
        for (int cio = 0; cio < 4; cio++) {
            float iv[12];
#pragma unroll
            for (int q = 0; q < 12; q++) iv[q] = in_row[cio][tw * 4 + q];
#pragma unroll
            for (int t = 0; t < 9; t++) {
#pragma unroll
                for (int i = 0; i < 8; i++) {
                    float wv = ws[((tm * 8 + i) * 4 + cio) * 9 + t];
                    acc[i][0] += wv * iv[t + 0];
                    acc[i][1] += wv * iv[t + 1];
                    acc[i][2] += wv * iv[t + 2];
                    acc[i][3] += wv * iv[t + 3];
                }
            }
        }
    }

    const float wsc = 0.029462782549439476f; // 1/sqrt(1152)
#pragma unroll
    for (int i = 0; i < 8; i++) {
        int m = g * 128 + tm * 8 + i;
        float cm = cvec[m];
        float4 o;
        float* po = (float*)&o;
#pragma unroll
        for (int w = 0; w < 4; w++) {
            float val = acc[i][w] * wsc * cm;
            float sg = 1.f / (1.f + __expf(-val));
            po[w] = val * sg * 1.6778523489932886f; // silu / 0.596
        }
        *(float4*)&y2[(size_t)m * L + h * WWID + wt * 64 + tw * 4] = o;
    }
}

// ---------------- normalize qk over d, split + pack q/k as [h][d][L] ----------------
__global__ void qknorm_k(const float* __restrict__ qk, float* __restrict__ qo,
                         float* __restrict__ ko) {
    int l = blockIdx.x * 256 + threadIdx.x;
    int h = blockIdx.y >> 1, s = blockIdx.y & 1;
    const float* base = qk + (size_t)(h * 256 + s) * L + l;
    float sum = 0.f;
#pragma unroll 8
    for (int d = 0; d < 128; d++) { float v = base[(size_t)d * 2 * L]; sum += v * v; }
    float inv = 1.f / (MP_EPS + sqrtf(sum) * 0.08838834764831845f); // 1/sqrt(128)
    float* out = (s ? ko : qo) + (size_t)h * 128 * L + l;
#pragma unroll 8
    for (int d = 0; d < 128; d++) out[(size_t)d * L] = base[(size_t)d * 2 * L] * inv;
}

// ---------------- normalize v over d, in place ----------------
__global__ void vnorm_k(float* __restrict__ v) {
    int l = blockIdx.x * 256 + threadIdx.x;
    int h = blockIdx.y;
    float* base = v + (size_t)h * 128 * L + l;
    float sum = 0.f;
#pragma unroll 8
    for (int d = 0; d < 128; d++) { float t = base[(size_t)d * L]; sum += t * t; }
    float inv = 1.f / (MP_EPS + sqrtf(sum) * 0.08838834764831845f);
#pragma unroll 8
    for (int d = 0; d < 128; d++) base[(size_t)d * L] *= inv;
}

// ---------------- flash attention, tf32 tensor cores, fused mp_sum + clip ----------------
// BQ=128, BKV=64, d=128. 8 warps: wm=wid>>1 (4 row-blocks of 32), wn=wid&1 (2 col-blocks).
#define QS_OFF  0
#define KS_OFF  17408
#define VS_OFF  26624
#define PS_OFF  35840
#define RM_OFF  44544
#define RS_OFF  44800
#define ATTN_SMEM_FLOATS 45056

#define MMA_TF32(d0,d1,d2,d3,a0,a1,a2,a3,b0,b1) \
  asm volatile("mma.sync.aligned.m16n8k8.row.col.f32.tf32.tf32.f32 " \
    "{%0,%1,%2,%3}, {%4,%5,%6,%7}, {%8,%9}, {%0,%1,%2,%3};" \
    : "+f"(d0),"+f"(d1),"+f"(d2),"+f"(d3) \
    : "r"(a0),"r"(a1),"r"(a2),"r"(a3),"r"(b0),"r"(b1))

__global__ void __launch_bounds__(256, 1) attn_k(
    const float* __restrict__ q, const float* __restrict__ k, const float* __restrict__ v,
    const float* __restrict__ x1, float* __restrict__ out) {
    extern __shared__ float sm[];
    float* qs   = sm + QS_OFF;
    float* ks   = sm + KS_OFF;
    float* vs   = sm + VS_OFF;
    float* ps   = sm + PS_OFF;
    float* redm = sm + RM_OFF;
    float* reds = sm + RS_OFF;

    const int tid = threadIdx.x;
    const int lane = tid & 31;
    const int g = lane >> 2;      // fragment row group
    const int t = lane & 3;       // thread-in-group
    const int wid = tid >> 5;
    const int wm = wid >> 1;      // 0..3: 32-row block
    const int wn = wid & 1;       // 0..1: col block
    const int hd = blockIdx.y, qt = blockIdx.x;

    const float* qh = q + (size_t)hd * 128 * L + qt * 128;
    const float* kh = k + (size_t)hd * 128 * L;
    const float* vh = v + (size_t)hd * 128 * L;

    // load Q tile [d][m], 1/sqrt(d) folded, rounded to tf32
    for (int idx = tid * 4; idx < 16384; idx += 1024) {
        int d = idx >> 7, i = idx & 127;
        float4 tq = *(const float4*)(qh + (size_t)d * L + i);
        tq.x = tf32r(tq.x * 0.08838834764831845f);
        tq.y = tf32r(tq.y * 0.08838834764831845f);
        tq.z = tf32r(tq.z * 0.08838834764831845f);
        tq.w = tf32r(tq.w * 0.08838834764831845f);
        *(float4*)(qs + d * 136 + i) = tq;
    }

    float o[2][8][4];
#pragma unroll
    for (int mt = 0; mt < 2; mt++)
#pragma unroll
        for (int nt = 0; nt < 8; nt++)
#pragma unroll
            for (int c = 0; c < 4; c++) o[mt][nt][c] = 0.f;
    float mrow[2][2] = {{-1e30f, -1e30f}, {-1e30f, -1e30f}};
    float lrow[2][2] = {{0.f, 0.f}, {0.f, 0.f}};

    for (int kt = 0; kt < 128; kt++) {
        __syncthreads(); // prev PV / reds reads done before overwriting tiles
        for (int idx = tid * 4; idx < 8192; idx += 1024) {
            int d = idx >> 6, j = idx & 63;
            float4 tk = *(const float4*)(kh + (size_t)d * L + kt * 64 + j);
            tk.x = tf32r(tk.x); tk.y = tf32r(tk.y); tk.z = tf32r(tk.z); tk.w = tf32r(tk.w);
            *(float4*)(ks + d * 72 + j) = tk;
            float4 tv = *(const float4*)(vh + (size_t)d * L + kt * 64 + j);
            tv.x = tf32r(tv.x); tv.y = tf32r(tv.y); tv.z = tf32r(tv.z); tv.w = tf32r(tv.w);
            *(float4*)(vs + d * 72 + j) = tv;
        }
        __syncthreads();

        // ---- S = Q^T K (tf32 MMA), each warp 32x32 ----
        float s[2][4][4];
#pragma unroll
        for (int mt = 0; mt < 2; mt++)
#pragma unroll
            for (int nt = 0; nt < 4; nt++)
#pragma unroll
                for (int c = 0; c < 4; c++) s[mt][nt][c] = 0.f;

#pragma unroll
        for (int k8 = 0; k8 < 16; k8++) {
            const int d0 = k8 * 8;
            unsigned a[2][4], b[4][2];
#pragma unroll
            for (int mt = 0; mt < 2; mt++) {
                int m = wm * 32 + mt * 16 + g;
                a[mt][0] = __float_as_uint(qs[(d0 + t) * 136 + m]);
                a[mt][1] = __float_as_uint(qs[(d0 + t) * 136 + m + 8]);
                a[mt][2] = __float_as_uint(qs[(d0 + t + 4) * 136 + m]);
                a[mt][3] = __float_as_uint(qs[(d0 + t + 4) * 136 + m + 8]);
            }
#pragma unroll
            for (int nt = 0; nt < 4; nt++) {
                int n = wn * 32 + nt * 8 + g;
                b[nt][0] = __float_as_uint(ks[(d0 + t) * 72 + n]);
                b[nt][1] = __float_as_uint(ks[(d0 + t + 4) * 72 + n]);
            }
#pragma unroll
            for (int mt = 0; mt < 2; mt++)
#pragma unroll
                for (int nt = 0; nt < 4; nt++)
                    MMA_TF32(s[mt][nt][0], s[mt][nt][1], s[mt][nt][2], s[mt][nt][3],
                             a[mt][0], a[mt][1], a[mt][2], a[mt][3], b[nt][0], b[nt][1]);
        }

        // ---- online softmax: local row max over 32 cols, exchange across wn ----
#pragma unroll
        for (int mt = 0; mt < 2; mt++)
#pragma unroll
            for (int rs = 0; rs < 2; rs++) {
                float mx = -1e30f;
#pragma unroll
                for (int nt = 0; nt < 4; nt++)
                    mx = fmaxf(mx, fmaxf(s[mt][nt][rs * 2], s[mt][nt][rs * 2 + 1]));
                mx = fmaxf(mx, __shfl_xor_sync(0xffffffffu, mx, 1));
                mx = fmaxf(mx, __shfl_xor_sync(0xffffffffu, mx, 2));
                if (t == 0) redm[wn * 128 + wm * 32 + mt * 16 + rs * 8 + g] = mx;
            }
        __syncthreads();

        float corr2[2][2];
#pragma unroll
        for (int mt = 0; mt < 2; mt++)
#pragma unroll
            for (int rs = 0; rs < 2; rs++) {
                int row = wm * 32 + mt * 16 + rs * 8 + g;
                float gm = fmaxf(redm[row], redm[128 + row]);
                float mnew = fmaxf(mrow[mt][rs], gm);
                float corr = __expf(mrow[mt][rs] - mnew);
                mrow[mt][rs] = mnew;
                corr2[mt][rs] = corr;
                float ls = 0.f;
#pragma unroll
                for (int nt = 0; nt < 4; nt++) {
#pragma unroll
                    for (int cc = 0; cc < 2; cc++) {
                        float p = __expf(s[mt][nt][rs * 2 + cc] - mnew);
                        ls += p;
                        ps[(wn * 32 + nt * 8 + 2 * t + cc) * 136 + row] = p;
                    }
                }
                ls += __shfl_xor_sync(0xffffffffu, ls, 1);
                ls += __shfl_xor_sync(0xffffffffu, ls, 2);
                if (t == 0) reds[wn * 128 + row] = ls;
#pragma unroll
                for (int nt = 0; nt < 8; nt++) {
                    o[mt][nt][rs * 2] *= corr;
                    o[mt][nt][rs * 2 + 1] *= corr;
                }
            }
        __syncthreads();
#pragma unroll
        for (int mt = 0; mt < 2; mt++)
#pragma unroll
            for (int rs = 0; rs < 2; rs++) {
                int row = wm * 32 + mt * 16 + rs * 8 + g;
                lrow[mt][rs] = lrow[mt][rs] * corr2[mt][rs] + reds[row] + reds[128 + row];
            }

        // ---- O += P V (each warp 32 rows x 64 dv cols) ----
#pragma unroll
        for (int kk = 0; kk < 8; kk++) {
            unsigned a[2][4];
#pragma unroll
            for (int mt = 0; mt < 2; mt++) {
                int m = wm * 32 + mt * 16 + g;
                a[mt][0] = __float_as_uint(ps[(kk * 8 + t) * 136 + m]);
                a[mt][1] = __float_as_uint(ps[(kk * 8 + t) * 136 + m + 8]);
                a[mt][2] = __float_as_uint(ps[(kk * 8 + t + 4) * 136 + m]);
                a[mt][3] = __float_as_uint(ps[(kk * 8 + t + 4) * 136 + m + 8]);
            }
#pragma unroll
            for (int nt = 0; nt < 8; nt++) {
                int dv = wn * 64 + nt * 8 + g;
                unsigned b0 = __float_as_uint(vs[dv * 72 + kk * 8 + t]);
                unsigned b1 = __float_as_uint(vs[dv * 72 + kk * 8 + t + 4]);
#pragma unroll
                for (int mt = 0; mt < 2; mt++)
                    MMA_TF32(o[mt][nt][0], o[mt][nt][1], o[mt][nt][2], o[mt][nt][3],
                             a[mt][0], a[mt][1], a[mt][2], a[mt][3], b0, b1);
            }
        }
    }

    // ---- epilogue: normalize, residual mp_sum, clip, store ----
#pragma unroll
    for (int mt = 0; mt < 2; mt++)
#pragma unroll
        for (int rs = 0; rs < 2; rs++) {
            float invl = 1.f / lrow[mt][rs];
            int i = qt * 128 + wm * 32 + mt * 16 + rs * 8 + g;
#pragma unroll
            for (int nt = 0; nt < 8; nt++) {
#pragma unroll
                for (int cc = 0; cc < 2; cc++) {
                    int ch = hd * 128 + wn * 64 + nt * 8 + 2 * t + cc;
                    float val = o[mt][nt][rs * 2 + cc] * invl;
                    float res = (x1[(size_t)ch * L + i] + val) * 0.7071067811865476f;
                    res = fminf(fmaxf(res, -256.f), 256.f);
                    out[(size_t)ch * L + i] = res;
                }
            }
        }
}

// ---------------- launch ----------------
extern "C" void kernel_launch(void* const* d_in, const int* in_sizes, int n_in,
                              void* d_out, int out_size) {
    const float* x      = (const float*)d_in[0];
    const float* emb    = (const float*)d_in[1];
    const float* pos    = (const float*)d_in[2];
    const float* egain  = (const float*)d_in[3];
    const float* w_res0 = (const float*)d_in[4];
    const float* w_dep  = (const float*)d_in[5];
    const float* w_emb  = (const float*)d_in[6];
    const float* w_res1 = (const float*)d_in[7];
    const float* w_qk   = (const float*)d_in[8];
    const float* w_v    = (const float*)d_in[9];
    float* outp = (float*)d_out;

    float *xn, *y0, *y2, *x1, *pe, *qkb, *qb, *kb, *vb, *cv;
    cudaGetSymbolAddress((void**)&xn, g_xn);
    cudaGetSymbolAddress((void**)&y0, g_y0);
    cudaGetSymbolAddress((void**)&y2, g_y2);
    cudaGetSymbolAddress((void**)&x1, g_x1);
    cudaGetSymbolAddress((void**)&pe, g_pe);
    cudaGetSymbolAddress((void**)&qkb, g_qk);
    cudaGetSymbolAddress((void**)&qb, g_q);
    cudaGetSymbolAddress((void**)&kb, g_k);
    cudaGetSymbolAddress((void**)&vb, g_v);
    cudaGetSymbolAddress((void**)&cv, g_c);

    const float rs512  = 0.044194173824159216f; // 1/sqrt(512)
    const float rs1024 = 0.03125f;              // 1/sqrt(1024)

    norm_x_k<<<32, 256>>>(x, xn);
    emb_k<<<128, 256>>>(emb, w_emb, egain, cv);

    // y0 = res0(xn): [1024,512] @ [512,L]
    sgemm_k<0><<<dim3(64, 8), 256>>>(w_res0, xn, y0, MM, L, CC, rs512, 0, 0, 0);
    // depth conv + c-mod + silu
    depth_k<<<dim3(8, 16, 8), 256>>>(y0, w_dep, cv, y2);
    // x1 = (xn + res1(y2))/sqrt2 ; pe interleave. [512,1024] @ [1024,L]
    sgemm_k<1><<<dim3(64, 4), 256>>>(w_res1, y2, x1, CC, L, MM, rs1024, xn, pos, pe);
    // qk = Wqk @ pe: [1024,1024] @ [1024,L]
    sgemm_k<0><<<dim3(64, 8), 256>>>(w_qk, pe, qkb, MM, L, MM, rs1024, 0, 0, 0);
    // v = Wv @ x1: [512,512] @ [512,L]
    sgemm_k<0><<<dim3(64, 4), 256>>>(w_v, x1, vb, CC, L, CC, rs512, 0, 0, 0);

    qknorm_k<<<dim3(32, 8), 256>>>(qkb, qb, kb);
    vnorm_k<<<dim3(32, 4), 256>>>(vb);

    const int SMEM = ATTN_SMEM_FLOATS * 4; // 180224 B
    cudaFuncSetAttribute(attn_k, cudaFuncAttributeMaxDynamicSharedMemorySize, SMEM);
    attn_k<<<dim3(64, 4), 256, SMEM>>>(qb, kb, vb, x1, outp);
}

// round 13
// speedup vs baseline: 2.6995x; 1.0089x over previous
#include <cuda_runtime.h>
#include <math.h>

#define L    8192
#define CC   512
#define MM   1024
#define HH   16
#define WWID 512
#define NHEADS 4
#define DHEAD  128
#define MP_EPS 1e-4f

// ---------------- scratch (static device allocations; no cudaMalloc) ----------------
__device__ float g_xn[CC * L];    // normalized x
__device__ float g_y0[MM * L];    // res0 output
__device__ float g_y2[MM * L];    // depth conv + silu output
__device__ float g_x1[CC * L];    // x after mp_sum with residual branch
__device__ float g_pe[MM * L];    // interleaved [x, x*pos]
__device__ float g_qk[MM * L];    // qk conv output (pre-norm)
__device__ float g_q[CC * L];     // packed q [h][d][L]
__device__ float g_k[CC * L];     // packed k [h][d][L]
__device__ float g_v[CC * L];     // v (normalized in place) [h*128+d][L]
__device__ float g_c[MM];         // embedding modulation vector

__device__ __forceinline__ float tf32r(float x) {
    float r;
    asm("cvt.rna.tf32.f32 %0, %1;" : "=f"(r) : "f"(x));
    return r;
}

// ---------------- normalize x over channels (per pixel) ----------------
__global__ void norm_x_k(const float* __restrict__ x, float* __restrict__ xn) {
    int l = blockIdx.x * 256 + threadIdx.x;
    float s = 0.f;
#pragma unroll 8
    for (int c = 0; c < CC; c++) { float v = x[c * L + l]; s += v * v; }
    float inv = 1.f / (MP_EPS + sqrtf(s) * 0.044194173824159216f); // 1/sqrt(512)
#pragma unroll 8
    for (int c = 0; c < CC; c++) xn[c * L + l] = x[c * L + l] * inv;
}

// ---------------- c[m] = emb_gain/sqrt(512) * (w_emb[m] . emb) + 1 ----------------
__global__ void emb_k(const float* __restrict__ emb, const float* __restrict__ wemb,
                      const float* __restrict__ gain, float* __restrict__ cvec) {
    int m = blockIdx.x * 8 + (threadIdx.x >> 5);
    int lane = threadIdx.x & 31;
    float s = 0.f;
    for (int e = lane; e < 512; e += 32) s += wemb[m * 512 + e] * emb[e];
#pragma unroll
    for (int off = 16; off; off >>= 1) s += __shfl_xor_sync(0xffffffffu, s, off);
    if (lane == 0) cvec[m] = gain[0] * 0.044194173824159216f * s + 1.f;
}

// ---------------- SGEMM: C[M,N] = scale * A[M,K] @ B[K,N] ----------------
template <int EPI>
__global__ void __launch_bounds__(256) sgemm_k(
    const float* __restrict__ A, const float* __restrict__ B, float* __restrict__ C,
    int M, int N, int K, float scale,
    const float* __restrict__ xn, const float* __restrict__ pos, float* __restrict__ pe) {
    __shared__ float As[8][132];
    __shared__ float Bs[8][128];
    const int tid = threadIdx.x;
    const int row0 = blockIdx.y * 128, col0 = blockIdx.x * 128;
    const int arow = tid >> 1, acol = (tid & 1) * 4;
    const int brow = tid >> 5, bcol = (tid & 31) * 4;
    const int ty = tid >> 4, tx = tid & 15;

    float acc[8][8];
#pragma unroll
    for (int i = 0; i < 8; i++)
#pragma unroll
        for (int j = 0; j < 8; j++) acc[i][j] = 0.f;

    const float* Aptr = A + (row0 + arow) * K + acol;
    const float* Bptr = B + brow * N + col0 + bcol;

    for (int k0 = 0; k0 < K; k0 += 8) {
        float4 av = *(const float4*)(Aptr + k0);
        float4 bv = *(const float4*)(Bptr + (size_t)k0 * N);
        As[acol + 0][arow] = av.x;
        As[acol + 1][arow] = av.y;
        As[acol + 2][arow] = av.z;
        As[acol + 3][arow] = av.w;
        *(float4*)&Bs[brow][bcol] = bv;
        __syncthreads();
#pragma unroll
        for (int kk = 0; kk < 8; kk++) {
            float a[8], b[8];
            *(float4*)(a)     = *(const float4*)&As[kk][ty * 8];
            *(float4*)(a + 4) = *(const float4*)&As[kk][ty * 8 + 4];
            *(float4*)(b)     = *(const float4*)&Bs[kk][tx * 8];
            *(float4*)(b + 4) = *(const float4*)&Bs[kk][tx * 8 + 4];
#pragma unroll
            for (int i = 0; i < 8; i++)
#pragma unroll
                for (int j = 0; j < 8; j++) acc[i][j] += a[i] * b[j];
        }
        __syncthreads();
    }

#pragma unroll
    for (int i = 0; i < 8; i++) {
        int r = row0 + ty * 8 + i;
        int cbase = col0 + tx * 8;
        if (EPI == 0) {
            float4 o0, o1;
            o0.x = acc[i][0] * scale; o0.y = acc[i][1] * scale;
            o0.z = acc[i][2] * scale; o0.w = acc[i][3] * scale;
            o1.x = acc[i][4] * scale; o1.y = acc[i][5] * scale;
            o1.z = acc[i][6] * scale; o1.w = acc[i][7] * scale;
            *(float4*)&C[(size_t)r * N + cbase]     = o0;
            *(float4*)&C[(size_t)r * N + cbase + 4] = o1;
        } else {
#pragma unroll
            for (int j = 0; j < 8; j++) {
                int n = cbase + j;
                float val = (xn[(size_t)r * N + n] + acc[i][j] * scale) * 0.7071067811865476f;
                C[(size_t)r * N + n] = val;
                pe[(size_t)(2 * r) * N + n] = val;
                pe[(size_t)(2 * r + 1) * N + n] = val * pos[(size_t)r * N + n];
            }
        }
    }
}

// ---------------- grouped (1,9) conv + c-mod + mp_silu, fused (ci tiled by 4) ----------------
// grid: (wtile=8, h=16, group=8), 256 threads. Block computes 128 m x 64 w.
__global__ void __launch_bounds__(256) depth_k(const float* __restrict__ y0,
                                               const float* __restrict__ wd,
                                               const float* __restrict__ cvec,
                                               float* __restrict__ y2) {
    __shared__ float ws[4608];      // [m 128][cio 4][tap 9]
    __shared__ float in_row[4][72]; // 4 input rows (64 + 8 halo)
    const int tid = threadIdx.x;
    const int wt = blockIdx.x, h = blockIdx.y, g = blockIdx.z;
    const int tm = tid >> 4, tw = tid & 15;

    float acc[8][4];
#pragma unroll
    for (int i = 0; i < 8; i++)
#pragma unroll
        for (int w = 0; w < 4; w++) acc[i][w] = 0.f;

    const float* wbase = wd + (size_t)g * 128 * 1152;
    const float* ybase = y0 + (size_t)(g * 128) * L + h * WWID;

    for (int ci0 = 0; ci0 < 128; ci0 += 4) {
        __syncthreads();
#pragma unroll
        for (int q = tid; q < 512; q += 256) {
            int m = q >> 2, cio = q & 3;
            const float* src = wbase + m * 1152 + (ci0 + cio) * 9;
            float* dst = ws + (m * 4 + cio) * 9;
#pragma unroll
            for (int t = 0; t < 9; t++) dst[t] = src[t];
        }
        // 288 halo elements, 256 threads -> strided loop (NOT a single if!)
        for (int q = tid; q < 288; q += 256) {
            int cio = q / 72, off = q - cio * 72;
            int w = wt * 64 - 4 + off;
            in_row[cio][off] = ((unsigned)w < WWID) ? ybase[(size_t)(ci0 + cio) * L + w] : 0.f;
        }
        __syncthreads();
#pragma unroll
        for (int cio = 0; cio < 4; cio++) {
            float iv[12];
#pragma unroll
            for (int q = 0; q < 12; q++) iv[q] = in_row[cio][tw * 4 + q];
#pragma unroll
            for (int t = 0; t < 9; t++) {
#pragma unroll
                for (int i = 0; i < 8; i++) {
                    float wv = ws[((tm * 8 + i) * 4 + cio) * 9 + t];
                    acc[i][0] += wv * iv[t + 0];
                    acc[i][1] += wv * iv[t + 1];
                    acc[i][2] += wv * iv[t + 2];
                    acc[i][3] += wv * iv[t + 3];
                }
            }
        }
    }

    const float wsc = 0.029462782549439476f; // 1/sqrt(1152)
#pragma unroll
    for (int i = 0; i < 8; i++) {
        int m = g * 128 + tm * 8 + i;
        float cm = cvec[m];
        float4 o;
        float* po = (float*)&o;
#pragma unroll
        for (int w = 0; w < 4; w++) {
            float val = acc[i][w] * wsc * cm;
            float sg = 1.f / (1.f + __expf(-val));
            po[w] = val * sg * 1.6778523489932886f; // silu / 0.596
        }
        *(float4*)&y2[(size_t)m * L + h * WWID + wt * 64 + tw * 4] = o;
    }
}

// ---------------- normalize qk over d, split + pack q/k as [h][d][L] ----------------
__global__ void qknorm_k(const float* __restrict__ qk, float* __restrict__ qo,
                         float* __restrict__ ko) {
    int l = blockIdx.x * 256 + threadIdx.x;
    int h = blockIdx.y >> 1, s = blockIdx.y & 1;
    const float* base = qk + (size_t)(h * 256 + s) * L + l;
    float sum = 0.f;
#pragma unroll 8
    for (int d = 0; d < 128; d++) { float v = base[(size_t)d * 2 * L]; sum += v * v; }
    float inv = 1.f / (MP_EPS + sqrtf(sum) * 0.08838834764831845f); // 1/sqrt(128)
    float* out = (s ? ko : qo) + (size_t)h * 128 * L + l;
#pragma unroll 8
    for (int d = 0; d < 128; d++) out[(size_t)d * L] = base[(size_t)d * 2 * L] * inv;
}

// ---------------- normalize v over d, in place ----------------
__global__ void vnorm_k(float* __restrict__ v) {
    int l = blockIdx.x * 256 + threadIdx.x;
    int h = blockIdx.y;
    float* base = v + (size_t)h * 128 * L + l;
    float sum = 0.f;
#pragma unroll 8
    for (int d = 0; d < 128; d++) { float t = base[(size_t)d * L]; sum += t * t; }
    float inv = 1.f / (MP_EPS + sqrtf(sum) * 0.08838834764831845f);
#pragma unroll 8
    for (int d = 0; d < 128; d++) base[(size_t)d * L] *= inv;
}

// ---------------- flash attention, tf32 tensor cores, fused mp_sum + clip ----------------
// BQ=128, BKV=64, d=128. 8 warps: wm=wid>>1 (4 row-blocks of 32), wn=wid&1 (2 col-blocks).
#define QS_OFF  0
#define KS_OFF  17408
#define VS_OFF  26624
#define PS_OFF  35840
#define RM_OFF  44544
#define RS_OFF  44800
#define ATTN_SMEM_FLOATS 45056

#define MMA_TF32(d0,d1,d2,d3,a0,a1,a2,a3,b0,b1) \
  asm volatile("mma.sync.aligned.m16n8k8.row.col.f32.tf32.tf32.f32 " \
    "{%0,%1,%2,%3}, {%4,%5,%6,%7}, {%8,%9}, {%0,%1,%2,%3};" \
    : "+f"(d0),"+f"(d1),"+f"(d2),"+f"(d3) \
    : "r"(a0),"r"(a1),"r"(a2),"r"(a3),"r"(b0),"r"(b1))

__global__ void __launch_bounds__(256, 1) attn_k(
    const float* __restrict__ q, const float* __restrict__ k, const float* __restrict__ v,
    const float* __restrict__ x1, float* __restrict__ out) {
    extern __shared__ float sm[];
    float* qs   = sm + QS_OFF;
    float* ks   = sm + KS_OFF;
    float* vs   = sm + VS_OFF;
    float* ps   = sm + PS_OFF;
    float* redm = sm + RM_OFF;
    float* reds = sm + RS_OFF;

    const int tid = threadIdx.x;
    const int lane = tid & 31;
    const int g = lane >> 2;      // fragment row group
    const int t = lane & 3;       // thread-in-group
    const int wid = tid >> 5;
    const int wm = wid >> 1;      // 0..3: 32-row block
    const int wn = wid & 1;       // 0..1: col block
    const int hd = blockIdx.y, qt = blockIdx.x;

    const float* qh = q + (size_t)hd * 128 * L + qt * 128;
    const float* kh = k + (size_t)hd * 128 * L;
    const float* vh = v + (size_t)hd * 128 * L;

    // load Q tile [d][m], 1/sqrt(d) folded, rounded to tf32
    for (int idx = tid * 4; idx < 16384; idx += 1024) {
        int d = idx >> 7, i = idx & 127;
        float4 tq = *(const float4*)(qh + (size_t)d * L + i);
        tq.x = tf32r(tq.x * 0.08838834764831845f);
        tq.y = tf32r(tq.y * 0.08838834764831845f);
        tq.z = tf32r(tq.z * 0.08838834764831845f);
        tq.w = tf32r(tq.w * 0.08838834764831845f);
        *(float4*)(qs + d * 136 + i) = tq;
    }

    float o[2][8][4];
#pragma unroll
    for (int mt = 0; mt < 2; mt++)
#pragma unroll
        for (int nt = 0; nt < 8; nt++)
#pragma unroll
            for (int c = 0; c < 4; c++) o[mt][nt][c] = 0.f;
    float mrow[2][2] = {{-1e30f, -1e30f}, {-1e30f, -1e30f}};
    float lrow[2][2] = {{0.f, 0.f}, {0.f, 0.f}};

    for (int kt = 0; kt < 128; kt++) {
        __syncthreads(); // prev PV / reds reads done before overwriting tiles
        for (int idx = tid * 4; idx < 8192; idx += 1024) {
            int d = idx >> 6, j = idx & 63;
            float4 tk = *(const float4*)(kh + (size_t)d * L + kt * 64 + j);
            tk.x = tf32r(tk.x); tk.y = tf32r(tk.y); tk.z = tf32r(tk.z); tk.w = tf32r(tk.w);
            *(float4*)(ks + d * 72 + j) = tk;
            float4 tv = *(const float4*)(vh + (size_t)d * L + kt * 64 + j);
            tv.x = tf32r(tv.x); tv.y = tf32r(tv.y); tv.z = tf32r(tv.z); tv.w = tf32r(tv.w);
            *(float4*)(vs + d * 72 + j) = tv;
        }
        __syncthreads();

        // ---- S = Q^T K (tf32 MMA), each warp 32x32 ----
        float s[2][4][4];
#pragma unroll
        for (int mt = 0; mt < 2; mt++)
#pragma unroll
            for (int nt = 0; nt < 4; nt++)
#pragma unroll
                for (int c = 0; c < 4; c++) s[mt][nt][c] = 0.f;

#pragma unroll
        for (int k8 = 0; k8 < 16; k8++) {
            const int d0 = k8 * 8;
            unsigned a[2][4], b[4][2];
#pragma unroll
            for (int mt = 0; mt < 2; mt++) {
                int m = wm * 32 + mt * 16 + g;
                a[mt][0] = __float_as_uint(qs[(d0 + t) * 136 + m]);
                a[mt][1] = __float_as_uint(qs[(d0 + t) * 136 + m + 8]);
                a[mt][2] = __float_as_uint(qs[(d0 + t + 4) * 136 + m]);
                a[mt][3] = __float_as_uint(qs[(d0 + t + 4) * 136 + m + 8]);
            }
#pragma unroll
            for (int nt = 0; nt < 4; nt++) {
                int n = wn * 32 + nt * 8 + g;
                b[nt][0] = __float_as_uint(ks[(d0 + t) * 72 + n]);
                b[nt][1] = __float_as_uint(ks[(d0 + t + 4) * 72 + n]);
            }
#pragma unroll
            for (int mt = 0; mt < 2; mt++)
#pragma unroll
                for (int nt = 0; nt < 4; nt++)
                    MMA_TF32(s[mt][nt][0], s[mt][nt][1], s[mt][nt][2], s[mt][nt][3],
                             a[mt][0], a[mt][1], a[mt][2], a[mt][3], b[nt][0], b[nt][1]);
        }

        // ---- online softmax: local row max over 32 cols, exchange across wn ----
#pragma unroll
        for (int mt = 0; mt < 2; mt++)
#pragma unroll
            for (int rs = 0; rs < 2; rs++) {
                float mx = -1e30f;
#pragma unroll
                for (int nt = 0; nt < 4; nt++)
                    mx = fmaxf(mx, fmaxf(s[mt][nt][rs * 2], s[mt][nt][rs * 2 + 1]));
                mx = fmaxf(mx, __shfl_xor_sync(0xffffffffu, mx, 1));
                mx = fmaxf(mx, __shfl_xor_sync(0xffffffffu, mx, 2));
                if (t == 0) redm[wn * 128 + wm * 32 + mt * 16 + rs * 8 + g] = mx;
            }
        __syncthreads();

        float corr2[2][2];
#pragma unroll
        for (int mt = 0; mt < 2; mt++)
#pragma unroll
            for (int rs = 0; rs < 2; rs++) {
                int row = wm * 32 + mt * 16 + rs * 8 + g;
                float gm = fmaxf(redm[row], redm[128 + row]);
                float mnew = fmaxf(mrow[mt][rs], gm);
                float corr = __expf(mrow[mt][rs] - mnew);
                mrow[mt][rs] = mnew;
                corr2[mt][rs] = corr;
                float ls = 0.f;
#pragma unroll
                for (int nt = 0; nt < 4; nt++) {
#pragma unroll
                    for (int cc = 0; cc < 2; cc++) {
                        float p = __expf(s[mt][nt][rs * 2 + cc] - mnew);
                        ls += p;
                        ps[(wn * 32 + nt * 8 + 2 * t + cc) * 136 + row] = p;
                    }
                }
                ls += __shfl_xor_sync(0xffffffffu, ls, 1);
                ls += __shfl_xor_sync(0xffffffffu, ls, 2);
                if (t == 0) reds[wn * 128 + row] = ls;
#pragma unroll
                for (int nt = 0; nt < 8; nt++) {
                    o[mt][nt][rs * 2] *= corr;
                    o[mt][nt][rs * 2 + 1] *= corr;
                }
            }
        __syncthreads();
#pragma unroll
        for (int mt = 0; mt < 2; mt++)
#pragma unroll
            for (int rs = 0; rs < 2; rs++) {
                int row = wm * 32 + mt * 16 + rs * 8 + g;
                lrow[mt][rs] = lrow[mt][rs] * corr2[mt][rs] + reds[row] + reds[128 + row];
            }

        // ---- O += P V (each warp 32 rows x 64 dv cols) ----
#pragma unroll
        for (int kk = 0; kk < 8; kk++) {
            unsigned a[2][4];
#pragma unroll
            for (int mt = 0; mt < 2; mt++) {
                int m = wm * 32 + mt * 16 + g;
                a[mt][0] = __float_as_uint(ps[(kk * 8 + t) * 136 + m]);
                a[mt][1] = __float_as_uint(ps[(kk * 8 + t) * 136 + m + 8]);
                a[mt][2] = __float_as_uint(ps[(kk * 8 + t + 4) * 136 + m]);
                a[mt][3] = __float_as_uint(ps[(kk * 8 + t + 4) * 136 + m + 8]);
            }
#pragma unroll
            for (int nt = 0; nt < 8; nt++) {
                int dv = wn * 64 + nt * 8 + g;
                unsigned b0 = __float_as_uint(vs[dv * 72 + kk * 8 + t]);
                unsigned b1 = __float_as_uint(vs[dv * 72 + kk * 8 + t + 4]);
#pragma unroll
                for (int mt = 0; mt < 2; mt++)
                    MMA_TF32(o[mt][nt][0], o[mt][nt][1], o[mt][nt][2], o[mt][nt][3],
                             a[mt][0], a[mt][1], a[mt][2], a[mt][3], b0, b1);
            }
        }
    }

    // ---- epilogue: normalize, residual mp_sum, clip, store ----
#pragma unroll
    for (int mt = 0; mt < 2; mt++)
#pragma unroll
        for (int rs = 0; rs < 2; rs++) {
            float invl = 1.f / lrow[mt][rs];
            int i = qt * 128 + wm * 32 + mt * 16 + rs * 8 + g;
#pragma unroll
            for (int nt = 0; nt < 8; nt++) {
#pragma unroll
                for (int cc = 0; cc < 2; cc++) {
                    int ch = hd * 128 + wn * 64 + nt * 8 + 2 * t + cc;
                    float val = o[mt][nt][rs * 2 + cc] * invl;
                    float res = (x1[(size_t)ch * L + i] + val) * 0.7071067811865476f;
                    res = fminf(fmaxf(res, -256.f), 256.f);
                    out[(size_t)ch * L + i] = res;
                }
            }
        }
}

// ---------------- launch ----------------
extern "C" void kernel_launch(void* const* d_in, const int* in_sizes, int n_in,
                              void* d_out, int out_size) {
    const float* x      = (const float*)d_in[0];
    const float* emb    = (const float*)d_in[1];
    const float* pos    = (const float*)d_in[2];
    const float* egain  = (const float*)d_in[3];
    const float* w_res0 = (const float*)d_in[4];
    const float* w_dep  = (const float*)d_in[5];
    const float* w_emb  = (const float*)d_in[6];
    const float* w_res1 = (const float*)d_in[7];
    const float* w_qk   = (const float*)d_in[8];
    const float* w_v    = (const float*)d_in[9];
    float* outp = (float*)d_out;

    float *xn, *y0, *y2, *x1, *pe, *qkb, *qb, *kb, *vb, *cv;
    cudaGetSymbolAddress((void**)&xn, g_xn);
    cudaGetSymbolAddress((void**)&y0, g_y0);
    cudaGetSymbolAddress((void**)&y2, g_y2);
    cudaGetSymbolAddress((void**)&x1, g_x1);
    cudaGetSymbolAddress((void**)&pe, g_pe);
    cudaGetSymbolAddress((void**)&qkb, g_qk);
    cudaGetSymbolAddress((void**)&qb, g_q);
    cudaGetSymbolAddress((void**)&kb, g_k);
    cudaGetSymbolAddress((void**)&vb, g_v);
    cudaGetSymbolAddress((void**)&cv, g_c);

    const float rs512  = 0.044194173824159216f; // 1/sqrt(512)
    const float rs1024 = 0.03125f;              // 1/sqrt(1024)

    norm_x_k<<<32, 256>>>(x, xn);
    emb_k<<<128, 256>>>(emb, w_emb, egain, cv);

    // y0 = res0(xn): [1024,512] @ [512,L]
    sgemm_k<0><<<dim3(64, 8), 256>>>(w_res0, xn, y0, MM, L, CC, rs512, 0, 0, 0);
    // depth conv + c-mod + silu
    depth_k<<<dim3(8, 16, 8), 256>>>(y0, w_dep, cv, y2);
    // x1 = (xn + res1(y2))/sqrt2 ; pe interleave. [512,1024] @ [1024,L]
    sgemm_k<1><<<dim3(64, 4), 256>>>(w_res1, y2, x1, CC, L, MM, rs1024, xn, pos, pe);
    // qk = Wqk @ pe: [1024,1024] @ [1024,L]
    sgemm_k<0><<<dim3(64, 8), 256>>>(w_qk, pe, qkb, MM, L, MM, rs1024, 0, 0, 0);
    // v = Wv @ x1: [512,512] @ [512,L]
    sgemm_k<0><<<dim3(64, 4), 256>>>(w_v, x1, vb, CC, L, CC, rs512, 0, 0, 0);

    qknorm_k<<<dim3(32, 8), 256>>>(qkb, qb, kb);
    vnorm_k<<<dim3(32, 4), 256>>>(vb);

    const int SMEM = ATTN_SMEM_FLOATS * 4; // 180224 B
    cudaFuncSetAttribute(attn_k, cudaFuncAttributeMaxDynamicSharedMemorySize, SMEM);
    attn_k<<<dim3(64, 4), 256, SMEM>>>(qb, kb, vb, x1, outp);
}

// round 14
// speedup vs baseline: 2.7014x; 1.0007x over previous
#include <cuda_runtime.h>
#include <math.h>

#define L    8192
#define CC   512
#define MM   1024
#define HH   16
#define WWID 512
#define NHEADS 4
#define DHEAD  128
#define MP_EPS 1e-4f

// ---------------- scratch (static device allocations; no cudaMalloc) ----------------
__device__ float g_xn[CC * L];    // normalized x
__device__ float g_y0[MM * L];    // res0 output
__device__ float g_y2[MM * L];    // depth conv + silu output
__device__ float g_x1[CC * L];    // x after mp_sum with residual branch
__device__ float g_pe[MM * L];    // interleaved [x, x*pos]
__device__ float g_qk[MM * L];    // qk conv output (pre-norm)
__device__ float g_q[CC * L];     // packed q [h][d][L]
__device__ float g_k[CC * L];     // packed k [h][d][L]
__device__ float g_v[CC * L];     // v (normalized in place) [h*128+d][L]
__device__ float g_c[MM];         // embedding modulation vector

__device__ __forceinline__ float tf32r(float x) {
    float r;
    asm("cvt.rna.tf32.f32 %0, %1;" : "=f"(r) : "f"(x));
    return r;
}

// ---------------- normalize x over channels (per pixel) ----------------
__global__ void norm_x_k(const float* __restrict__ x, float* __restrict__ xn) {
    int l = blockIdx.x * 256 + threadIdx.x;
    float s = 0.f;
#pragma unroll 8
    for (int c = 0; c < CC; c++) { float v = x[c * L + l]; s += v * v; }
    float inv = 1.f / (MP_EPS + sqrtf(s) * 0.044194173824159216f); // 1/sqrt(512)
#pragma unroll 8
    for (int c = 0; c < CC; c++) xn[c * L + l] = x[c * L + l] * inv;
}

// ---------------- c[m] = emb_gain/sqrt(512) * (w_emb[m] . emb) + 1 ----------------
__global__ void emb_k(const float* __restrict__ emb, const float* __restrict__ wemb,
                      const float* __restrict__ gain, float* __restrict__ cvec) {
    int m = blockIdx.x * 8 + (threadIdx.x >> 5);
    int lane = threadIdx.x & 31;
    float s = 0.f;
    for (int e = lane; e < 512; e += 32) s += wemb[m * 512 + e] * emb[e];
#pragma unroll
    for (int off = 16; off; off >>= 1) s += __shfl_xor_sync(0xffffffffu, s, off);
    if (lane == 0) cvec[m] = gain[0] * 0.044194173824159216f * s + 1.f;
}

// ---------------- SGEMM: C[M,N] = scale * A[M,K] @ B[K,N] ----------------
template <int EPI>
__global__ void __launch_bounds__(256) sgemm_k(
    const float* __restrict__ A, const float* __restrict__ B, float* __restrict__ C,
    int M, int N, int K, float scale,
    const float* __restrict__ xn, const float* __restrict__ pos, float* __restrict__ pe) {
    __shared__ float As[8][132];
    __shared__ float Bs[8][128];
    const int tid = threadIdx.x;
    const int row0 = blockIdx.y * 128, col0 = blockIdx.x * 128;
    const int arow = tid >> 1, acol = (tid & 1) * 4;
    const int brow = tid >> 5, bcol = (tid & 31) * 4;
    const int ty = tid >> 4, tx = tid & 15;

    float acc[8][8];
#pragma unroll
    for (int i = 0; i < 8; i++)
#pragma unroll
        for (int j = 0; j < 8; j++) acc[i][j] = 0.f;

    const float* Aptr = A + (row0 + arow) * K + acol;
    const float* Bptr = B + brow * N + col0 + bcol;

    for (int k0 = 0; k0 < K; k0 += 8) {
        float4 av = *(const float4*)(Aptr + k0);
        float4 bv = *(const float4*)(Bptr + (size_t)k0 * N);
        As[acol + 0][arow] = av.x;
        As[acol + 1][arow] = av.y;
        As[acol + 2][arow] = av.z;
        As[acol + 3][arow] = av.w;
        *(float4*)&Bs[brow][bcol] = bv;
        __syncthreads();
#pragma unroll
        for (int kk = 0; kk < 8; kk++) {
            float a[8], b[8];
            *(float4*)(a)     = *(const float4*)&As[kk][ty * 8];
            *(float4*)(a + 4) = *(const float4*)&As[kk][ty * 8 + 4];
            *(float4*)(b)     = *(const float4*)&Bs[kk][tx * 8];
            *(float4*)(b + 4) = *(const float4*)&Bs[kk][tx * 8 + 4];
#pragma unroll
            for (int i = 0; i < 8; i++)
#pragma unroll
                for (int j = 0; j < 8; j++) acc[i][j] += a[i] * b[j];
        }
        __syncthreads();
    }

#pragma unroll
    for (int i = 0; i < 8; i++) {
        int r = row0 + ty * 8 + i;
        int cbase = col0 + tx * 8;
        if (EPI == 0) {
            float4 o0, o1;
            o0.x = acc[i][0] * scale; o0.y = acc[i][1] * scale;
            o0.z = acc[i][2] * scale; o0.w = acc[i][3] * scale;
            o1.x = acc[i][4] * scale; o1.y = acc[i][5] * scale;
            o1.z = acc[i][6] * scale; o1.w = acc[i][7] * scale;
            *(float4*)&C[(size_t)r * N + cbase]     = o0;
            *(float4*)&C[(size_t)r * N + cbase + 4] = o1;
        } else {
#pragma unroll
            for (int j = 0; j < 8; j++) {
                int n = cbase + j;
                float val = (xn[(size_t)r * N + n] + acc[i][j] * scale) * 0.7071067811865476f;
                C[(size_t)r * N + n] = val;
                pe[(size_t)(2 * r) * N + n] = val;
                pe[(size_t)(2 * r + 1) * N + n] = val * pos[(size_t)r * N + n];
            }
        }
    }
}

// ---------------- grouped (1,9) conv + c-mod + mp_silu, fused (ci tiled by 4) ----------------
// grid: (wtile=8, h=16, group=8), 256 threads. Block computes 128 m x 64 w.
__global__ void __launch_bounds__(256) depth_k(const float* __restrict__ y0,
                                               const float* __restrict__ wd,
                                               const float* __restrict__ cvec,
                                               float* __restrict__ y2) {
    __shared__ float ws[4608];      // [m 128][cio 4][tap 9]
    __shared__ float in_row[4][72]; // 4 input rows (64 + 8 halo)
    const int tid = threadIdx.x;
    const int wt = blockIdx.x, h = blockIdx.y, g = blockIdx.z;
    const int tm = tid >> 4, tw = tid & 15;

    float acc[8][4];
#pragma unroll
    for (int i = 0; i < 8; i++)
#pragma unroll
        for (int w = 0; w < 4; w++) acc[i][w] = 0.f;

    const float* wbase = wd + (size_t)g * 128 * 1152;
    const float* ybase = y0 + (size_t)(g * 128) * L + h * WWID;

    for (int ci0 = 0; ci0 < 128; ci0 += 4) {
        __syncthreads();
#pragma unroll
        for (int q = tid; q < 512; q += 256) {
            int m = q >> 2, cio = q & 3;
            const float* src = wbase + m * 1152 + (ci0 + cio) * 9;
            float* dst = ws + (m * 4 + cio) * 9;
#pragma unroll
            for (int t = 0; t < 9; t++) dst[t] = src[t];
        }
        // 288 halo elements, 256 threads -> strided loop (NOT a single if!)
        for (int q = tid; q < 288; q += 256) {
            int cio = q / 72, off = q - cio * 72;
            int w = wt * 64 - 4 + off;
            in_row[cio][off] = ((unsigned)w < WWID) ? ybase[(size_t)(ci0 + cio) * L + w] : 0.f;
        }
        __syncthreads();
#pragma unroll
        for (int cio = 0; cio < 4; cio++) {
            float iv[12];
#pragma unroll
            for (int q = 0; q < 12; q++) iv[q] = in_row[cio][tw * 4 + q];
#pragma unroll
            for (int t = 0; t < 9; t++) {
#pragma unroll
                for (int i = 0; i < 8; i++) {
                    float wv = ws[((tm * 8 + i) * 4 + cio) * 9 + t];
                    acc[i][0] += wv * iv[t + 0];
                    acc[i][1] += wv * iv[t + 1];
                    acc[i][2] += wv * iv[t + 2];
                    acc[i][3] += wv * iv[t + 3];
                }
            }
        }
    }

    const float wsc = 0.029462782549439476f; // 1/sqrt(1152)
#pragma unroll
    for (int i = 0; i < 8; i++) {
        int m = g * 128 + tm * 8 + i;
        float cm = cvec[m];
        float4 o;
        float* po = (float*)&o;
#pragma unroll
        for (int w = 0; w < 4; w++) {
            float val = acc[i][w] * wsc * cm;
            float sg = 1.f / (1.f + __expf(-val));
            po[w] = val * sg * 1.6778523489932886f; // silu / 0.596
        }
        *(float4*)&y2[(size_t)m * L + h * WWID + wt * 64 + tw * 4] = o;
    }
}

// ---------------- normalize qk over d, split + pack q/k as [h][d][L] ----------------
__global__ void qknorm_k(const float* __restrict__ qk, float* __restrict__ qo,
                         float* __restrict__ ko) {
    int l = blockIdx.x * 256 + threadIdx.x;
    int h = blockIdx.y >> 1, s = blockIdx.y & 1;
    const float* base = qk + (size_t)(h * 256 + s) * L + l;
    float sum = 0.f;
#pragma unroll 8
    for (int d = 0; d < 128; d++) { float v = base[(size_t)d * 2 * L]; sum += v * v; }
    float inv = 1.f / (MP_EPS + sqrtf(sum) * 0.08838834764831845f); // 1/sqrt(128)
    float* out = (s ? ko : qo) + (size_t)h * 128 * L + l;
#pragma unroll 8
    for (int d = 0; d < 128; d++) out[(size_t)d * L] = base[(size_t)d * 2 * L] * inv;
}

// ---------------- normalize v over d, in place ----------------
__global__ void vnorm_k(float* __restrict__ v) {
    int l = blockIdx.x * 256 + threadIdx.x;
    int h = blockIdx.y;
    float* base = v + (size_t)h * 128 * L + l;
    float sum = 0.f;
#pragma unroll 8
    for (int d = 0; d < 128; d++) { float t = base[(size_t)d * L]; sum += t * t; }
    float inv = 1.f / (MP_EPS + sqrtf(sum) * 0.08838834764831845f);
#pragma unroll 8
    for (int d = 0; d < 128; d++) base[(size_t)d * L] *= inv;
}

// ---------------- flash attention, tf32 tensor cores, fused mp_sum + clip ----------------
// BQ=128, BKV=64, d=128. 8 warps: wm=wid>>1 (4 row-blocks of 32), wn=wid&1 (2 col-blocks).
#define QS_OFF  0
#define KS_OFF  17408
#define VS_OFF  26624
#define PS_OFF  35840
#define RM_OFF  44544
#define RS_OFF  44800
#define ATTN_SMEM_FLOATS 45056

#define MMA_TF32(d0,d1,d2,d3,a0,a1,a2,a3,b0,b1) \
  asm volatile("mma.sync.aligned.m16n8k8.row.col.f32.tf32.tf32.f32 " \
    "{%0,%1,%2,%3}, {%4,%5,%6,%7}, {%8,%9}, {%0,%1,%2,%3};" \
    : "+f"(d0),"+f"(d1),"+f"(d2),"+f"(d3) \
    : "r"(a0),"r"(a1),"r"(a2),"r"(a3),"r"(b0),"r"(b1))

__global__ void __launch_bounds__(256, 1) attn_k(
    const float* __restrict__ q, const float* __restrict__ k, const float* __restrict__ v,
    const float* __restrict__ x1, float* __restrict__ out) {
    extern __shared__ float sm[];
    float* qs   = sm + QS_OFF;
    float* ks   = sm + KS_OFF;
    float* vs   = sm + VS_OFF;
    float* ps   = sm + PS_OFF;
    float* redm = sm + RM_OFF;
    float* reds = sm + RS_OFF;

    const int tid = threadIdx.x;
    const int lane = tid & 31;
    const int g = lane >> 2;      // fragment row group
    const int t = lane & 3;       // thread-in-group
    const int wid = tid >> 5;
    const int wm = wid >> 1;      // 0..3: 32-row block
    const int wn = wid & 1;       // 0..1: col block
    const int hd = blockIdx.y, qt = blockIdx.x;

    const float* qh = q + (size_t)hd * 128 * L + qt * 128;
    const float* kh = k + (size_t)hd * 128 * L;
    const float* vh = v + (size_t)hd * 128 * L;

    // load Q tile [d][m], 1/sqrt(d) folded, rounded to tf32
    for (int idx = tid * 4; idx < 16384; idx += 1024) {
        int d = idx >> 7, i = idx & 127;
        float4 tq = *(const float4*)(qh + (size_t)d * L + i);
        tq.x = tf32r(tq.x * 0.08838834764831845f);
        tq.y = tf32r(tq.y * 0.08838834764831845f);
        tq.z = tf32r(tq.z * 0.08838834764831845f);
        tq.w = tf32r(tq.w * 0.08838834764831845f);
        *(float4*)(qs + d * 136 + i) = tq;
    }

    float o[2][8][4];
#pragma unroll
    for (int mt = 0; mt < 2; mt++)
#pragma unroll
        for (int nt = 0; nt < 8; nt++)
#pragma unroll
            for (int c = 0; c < 4; c++) o[mt][nt][c] = 0.f;
    float mrow[2][2] = {{-1e30f, -1e30f}, {-1e30f, -1e30f}};
    float lrow[2][2] = {{0.f, 0.f}, {0.f, 0.f}};

    for (int kt = 0; kt < 128; kt++) {
        __syncthreads(); // prev PV / reds reads done before overwriting tiles
        for (int idx = tid * 4; idx < 8192; idx += 1024) {
            int d = idx >> 6, j = idx & 63;
            float4 tk = *(const float4*)(kh + (size_t)d * L + kt * 64 + j);
            tk.x = tf32r(tk.x); tk.y = tf32r(tk.y); tk.z = tf32r(tk.z); tk.w = tf32r(tk.w);
            *(float4*)(ks + d * 72 + j) = tk;
            float4 tv = *(const float4*)(vh + (size_t)d * L + kt * 64 + j);
            tv.x = tf32r(tv.x); tv.y = tf32r(tv.y); tv.z = tf32r(tv.z); tv.w = tf32r(tv.w);
            *(float4*)(vs + d * 72 + j) = tv;
        }
        __syncthreads();

        // ---- S = Q^T K (tf32 MMA), each warp 32x32 ----
        float s[2][4][4];
#pragma unroll
        for (int mt = 0; mt < 2; mt++)
#pragma unroll
            for (int nt = 0; nt < 4; nt++)
#pragma unroll
                for (int c = 0; c < 4; c++) s[mt][nt][c] = 0.f;

#pragma unroll
        for (int k8 = 0; k8 < 16; k8++) {
            const int d0 = k8 * 8;
            unsigned a[2][4], b[4][2];
#pragma unroll
            for (int mt = 0; mt < 2; mt++) {
                int m = wm * 32 + mt * 16 + g;
                a[mt][0] = __float_as_uint(qs[(d0 + t) * 136 + m]);
                a[mt][1] = __float_as_uint(qs[(d0 + t) * 136 + m + 8]);
                a[mt][2] = __float_as_uint(qs[(d0 + t + 4) * 136 + m]);
                a[mt][3] = __float_as_uint(qs[(d0 + t + 4) * 136 + m + 8]);
            }
#pragma unroll
            for (int nt = 0; nt < 4; nt++) {
                int n = wn * 32 + nt * 8 + g;
                b[nt][0] = __float_as_uint(ks[(d0 + t) * 72 + n]);
                b[nt][1] = __float_as_uint(ks[(d0 + t + 4) * 72 + n]);
            }
#pragma unroll
            for (int mt = 0; mt < 2; mt++)
#pragma unroll
                for (int nt = 0; nt < 4; nt++)
                    MMA_TF32(s[mt][nt][0], s[mt][nt][1], s[mt][nt][2], s[mt][nt][3],
                             a[mt][0], a[mt][1], a[mt][2], a[mt][3], b[nt][0], b[nt][1]);
        }

        // ---- online softmax: local row max over 32 cols, exchange across wn ----
#pragma unroll
        for (int mt = 0; mt < 2; mt++)
#pragma unroll
            for (int rs = 0; rs < 2; rs++) {
                float mx = -1e30f;
#pragma unroll
                for (int nt = 0; nt < 4; nt++)
                    mx = fmaxf(mx, fmaxf(s[mt][nt][rs * 2], s[mt][nt][rs * 2 + 1]));
                mx = fmaxf(mx, __shfl_xor_sync(0xffffffffu, mx, 1));
                mx = fmaxf(mx, __shfl_xor_sync(0xffffffffu, mx, 2));
                if (t == 0) redm[wn * 128 + wm * 32 + mt * 16 + rs * 8 + g] = mx;
            }
        __syncthreads();

        float corr2[2][2];
#pragma unroll
        for (int mt = 0; mt < 2; mt++)
#pragma unroll
            for (int rs = 0; rs < 2; rs++) {
                int row = wm * 32 + mt * 16 + rs * 8 + g;
                float gm = fmaxf(redm[row], redm[128 + row]);
                float mnew = fmaxf(mrow[mt][rs], gm);
                float corr = __expf(mrow[mt][rs] - mnew);
                mrow[mt][rs] = mnew;
                corr2[mt][rs] = corr;
                float ls = 0.f;
#pragma unroll
                for (int nt = 0; nt < 4; nt++) {
#pragma unroll
                    for (int cc = 0; cc < 2; cc++) {
                        float p = __expf(s[mt][nt][rs * 2 + cc] - mnew);
                        ls += p;
                        ps[(wn * 32 + nt * 8 + 2 * t + cc) * 136 + row] = p;
                    }
                }
                ls += __shfl_xor_sync(0xffffffffu, ls, 1);
                ls += __shfl_xor_sync(0xffffffffu, ls, 2);
                if (t == 0) reds[wn * 128 + row] = ls;
#pragma unroll
                for (int nt = 0; nt < 8; nt++) {
                    o[mt][nt][rs * 2] *= corr;
                    o[mt][nt][rs * 2 + 1] *= corr;
                }
            }
        __syncthreads();
#pragma unroll
        for (int mt = 0; mt < 2; mt++)
#pragma unroll
            for (int rs = 0; rs < 2; rs++) {
                int row = wm * 32 + mt * 16 + rs * 8 + g;
                lrow[mt][rs] = lrow[mt][rs] * corr2[mt][rs] + reds[row] + reds[128 + row];
            }

        // ---- O += P V (each warp 32 rows x 64 dv cols) ----
#pragma unroll
        for (int kk = 0; kk < 8; kk++) {
            unsigned a[2][4];
#pragma unroll
            for (int mt = 0; mt < 2; mt++) {
                int m = wm * 32 + mt * 16 + g;
                a[mt][0] = __float_as_uint(ps[(kk * 8 + t) * 136 + m]);
                a[mt][1] = __float_as_uint(ps[(kk * 8 + t) * 136 + m + 8]);
                a[mt][2] = __float_as_uint(ps[(kk * 8 + t + 4) * 136 + m]);
                a[mt][3] = __float_as_uint(ps[(kk * 8 + t + 4) * 136 + m + 8]);
            }
#pragma unroll
            for (int nt = 0; nt < 8; nt++) {
                int dv = wn * 64 + nt * 8 + g;
                unsigned b0 = __float_as_uint(vs[dv * 72 + kk * 8 + t]);
                unsigned b1 = __float_as_uint(vs[dv * 72 + kk * 8 + t + 4]);
#pragma unroll
                for (int mt = 0; mt < 2; mt++)
                    MMA_TF32(o[mt][nt][0], o[mt][nt][1], o[mt][nt][2], o[mt][nt][3],
                             a[mt][0], a[mt][1], a[mt][2], a[mt][3], b0, b1);
            }
        }
    }

    // ---- epilogue: normalize, residual mp_sum, clip, store ----
#pragma unroll
    for (int mt = 0; mt < 2; mt++)
#pragma unroll
        for (int rs = 0; rs < 2; rs++) {
            float invl = 1.f / lrow[mt][rs];
            int i = qt * 128 + wm * 32 + mt * 16 + rs * 8 + g;
#pragma unroll
            for (int nt = 0; nt < 8; nt++) {
#pragma unroll
                for (int cc = 0; cc < 2; cc++) {
                    int ch = hd * 128 + wn * 64 + nt * 8 + 2 * t + cc;
                    float val = o[mt][nt][rs * 2 + cc] * invl;
                    float res = (x1[(size_t)ch * L + i] + val) * 0.7071067811865476f;
                    res = fminf(fmaxf(res, -256.f), 256.f);
                    out[(size_t)ch * L + i] = res;
                }
            }
        }
}

// ---------------- launch ----------------
extern "C" void kernel_launch(void* const* d_in, const int* in_sizes, int n_in,
                              void* d_out, int out_size) {
    const float* x      = (const float*)d_in[0];
    const float* emb    = (const float*)d_in[1];
    const float* pos    = (const float*)d_in[2];
    const float* egain  = (const float*)d_in[3];
    const float* w_res0 = (const float*)d_in[4];
    const float* w_dep  = (const float*)d_in[5];
    const float* w_emb  = (const float*)d_in[6];
    const float* w_res1 = (const float*)d_in[7];
    const float* w_qk   = (const float*)d_in[8];
    const float* w_v    = (const float*)d_in[9];
    float* outp = (float*)d_out;

    float *xn, *y0, *y2, *x1, *pe, *qkb, *qb, *kb, *vb, *cv;
    cudaGetSymbolAddress((void**)&xn, g_xn);
    cudaGetSymbolAddress((void**)&y0, g_y0);
    cudaGetSymbolAddress((void**)&y2, g_y2);
    cudaGetSymbolAddress((void**)&x1, g_x1);
    cudaGetSymbolAddress((void**)&pe, g_pe);
    cudaGetSymbolAddress((void**)&qkb, g_qk);
    cudaGetSymbolAddress((void**)&qb, g_q);
    cudaGetSymbolAddress((void**)&kb, g_k);
    cudaGetSymbolAddress((void**)&vb, g_v);
    cudaGetSymbolAddress((void**)&cv, g_c);

    const float rs512  = 0.044194173824159216f; // 1/sqrt(512)
    const float rs1024 = 0.03125f;              // 1/sqrt(1024)

    norm_x_k<<<32, 256>>>(x, xn);
    emb_k<<<128, 256>>>(emb, w_emb, egain, cv);

    // y0 = res0(xn): [1024,512] @ [512,L]
    sgemm_k<0><<<dim3(64, 8), 256>>>(w_res0, xn, y0, MM, L, CC, rs512, 0, 0, 0);
    // depth conv + c-mod + silu
    depth_k<<<dim3(8, 16, 8), 256>>>(y0, w_dep, cv, y2);
    // x1 = (xn + res1(y2))/sqrt2 ; pe interleave. [512,1024] @ [1024,L]
    sgemm_k<1><<<dim3(64, 4), 256>>>(w_res1, y2, x1, CC, L, MM, rs1024, xn, pos, pe);
    // qk = Wqk @ pe: [1024,1024] @ [1024,L]
    sgemm_k<0><<<dim3(64, 8), 256>>>(w_qk, pe, qkb, MM, L, MM, rs1024, 0, 0, 0);
    // v = Wv @ x1: [512,512] @ [512,L]
    sgemm_k<0><<<dim3(64, 4), 256>>>(w_v, x1, vb, CC, L, CC, rs512, 0, 0, 0);

    qknorm_k<<<dim3(32, 8), 256>>>(qkb, qb, kb);
    vnorm_k<<<dim3(32, 4), 256>>>(vb);

    const int SMEM = ATTN_SMEM_FLOATS * 4; // 180224 B
    cudaFuncSetAttribute(attn_k, cudaFuncAttributeMaxDynamicSharedMemorySize, SMEM);
    attn_k<<<dim3(64, 4), 256, SMEM>>>(qb, kb, vb, x1, outp);
}